// round 4
// baseline (speedup 1.0000x reference)
#include <cuda_runtime.h>

#define TPB 256

__device__ __forceinline__ float sp_f(float x) {      // fast softplus (~1e-7 rel)
    return fmaxf(x, 0.0f) + __logf(1.0f + __expf(-fabsf(x)));
}
__device__ __forceinline__ float sig_f(float x) {
    return 1.0f / (1.0f + __expf(-x));
}

// ---------------------------------------------------------------------------
// Fused kernel. Thread handles float4-column c of rows r, r+q, r+2q, r+3q.
// Coefficient tables built per-block (cheap, overlapped with x loads).
// ---------------------------------------------------------------------------
__global__ void __launch_bounds__(TPB, 4)
cb_fused(const float* __restrict__ x, float* __restrict__ out, int B, int q,
         const float* __restrict__ W,  const float* __restrict__ P,
         const float* __restrict__ bv, const float* __restrict__ bz,
         const float* __restrict__ e,  const float* __restrict__ ep,
         const float* __restrict__ cx, const float* __restrict__ cu,
         const float* __restrict__ cU, const float* __restrict__ v0,
         const float* __restrict__ X0, const float* __restrict__ U0)
{
    // Coefficient tables: ct_pd[i*6+c] = float4 of 0.1*P[4c..4c+3][i]
    //                     ct_pz[i*6+c] = float4 of pe*sp(P[4c..4c+3][i])
    __shared__ float4 ct_pd[48], ct_pz[48];
    __shared__ float4 c0q[6], a1q[6], zmq[6];
    __shared__ int   s_flag;
    __shared__ float rS[24], wS[24], pkr[192], pwr[192];

    const int t = threadIdx.x;

    // ---- issue x loads first: overlap their latency with the prologue ----
    const unsigned g = blockIdx.x * TPB + t;         // float4 index in quarter 0
    const unsigned nG = 6u * (unsigned)q;
    const bool live = (g < nG);
    const unsigned r = g / 6u;
    const unsigned c = g - r * 6u;

    float xv[4][8];
    #pragma unroll
    for (int k = 0; k < 4; ++k) {
        const int rk = (int)r + k * q;
        const bool ok = live && (rk < B);
        const float* xp = x + rk;
        #pragma unroll
        for (int i = 0; i < 8; ++i)
            xv[k][i] = ok ? __ldcs(xp + (size_t)i * (size_t)B) : 0.0f;
    }

    // ---- prologue: batch-invariant math ----
    if (t < 24) {
        float v0v = v0[t];
        float rv  = sig_f(v0v);
        rS[t] = rv;
        float zx = 0.001f + 0.099f * sig_f(cx[t]);
        float X  = zx + (1.0f - zx) * X0[t] - U0[t] * X0[t] * rv;   // delta_t = 1
        float zu   = 0.001f + 0.099f * sig_f(cu[t]);
        float Ucap = 0.9f * sig_f(cU[t]);
        float U = Ucap * zu + (1.0f - zu) * U0[t] + Ucap * (1.0f - U0[t]) * rv;
        U = fminf(fmaxf(U, Ucap), 1.0f);
        wS[t] = U * X * rv;
        ((float*)zmq)[t] = -0.1f * v0v;
    }
    if (t == 0) {
        int f = 0;
        #pragma unroll
        for (int j = 0; j < 24; ++j) f |= (v0[j] != 0.0f);
        s_flag = f;
    }
    __syncthreads();

    if (t < 192) {
        const int h = t >> 3;                    // 0..23
        const int i = t & 7;                     // 0..7
        float kr = 0.0f, wur = 0.0f;
        #pragma unroll
        for (int jj = 0; jj < 3; ++jj) {
            int j = i * 3 + jj;
            float Wv = W[h * 24 + j];
            kr  += sp_f(Wv) * rS[j];
            wur += Wv * wS[j];
        }
        pkr[h * 8 + i] = kr;
        pwr[h * 8 + i] = wur;
        float pe = sp_f(ep[0]);
        float Pv = P[h * 8 + i];                 // P is (H, IN) row-major
        ((float*)&ct_pd[i * 6 + (h >> 2)])[h & 3] = 0.1f * Pv;
        ((float*)&ct_pz[i * 6 + (h >> 2)])[h & 3] = pe * sp_f(Pv);
    }
    __syncthreads();

    if (t < 24) {
        float kr = 0.0f, wur = 0.0f;
        #pragma unroll
        for (int k = 0; k < 8; ++k) { kr += pkr[t * 8 + k]; wur += pwr[t * 8 + k]; }
        float ke = sp_f(e[0]);
        ((float*)a1q)[t] = ke * kr + bz[t];                      // a1
        ((float*)c0q)[t] = v0[t] + 0.1f * (wur + bv[t]);         // c0
    }
    __syncthreads();

    // ---- main: 4 rows x 4 h-values per thread, no further syncs ----
    if (!live) return;

    const float4 c0 = c0q[c];
    float4 acc[4];
    #pragma unroll
    for (int k = 0; k < 4; ++k) acc[k] = c0;

    #pragma unroll
    for (int i = 0; i < 8; ++i) {
        const float4 w4 = ct_pd[i * 6 + c];
        #pragma unroll
        for (int k = 0; k < 4; ++k) {
            acc[k].x = fmaf(w4.x, xv[k][i], acc[k].x);
            acc[k].y = fmaf(w4.y, xv[k][i], acc[k].y);
            acc[k].z = fmaf(w4.z, xv[k][i], acc[k].z);
            acc[k].w = fmaf(w4.w, xv[k][i], acc[k].w);
        }
    }

    if (s_flag) {
        // General case (v0 != 0): v += sig(a1 + Pz@x) * (-0.1*v0[h]). Exact.
        const float4 a1 = a1q[c];
        const float4 zm = zmq[c];
        float4 az[4];
        #pragma unroll
        for (int k = 0; k < 4; ++k) az[k] = a1;
        #pragma unroll
        for (int i = 0; i < 8; ++i) {
            const float4 z4 = ct_pz[i * 6 + c];
            #pragma unroll
            for (int k = 0; k < 4; ++k) {
                az[k].x = fmaf(z4.x, xv[k][i], az[k].x);
                az[k].y = fmaf(z4.y, xv[k][i], az[k].y);
                az[k].z = fmaf(z4.z, xv[k][i], az[k].z);
                az[k].w = fmaf(z4.w, xv[k][i], az[k].w);
            }
        }
        #pragma unroll
        for (int k = 0; k < 4; ++k) {
            acc[k].x = fmaf(zm.x, sig_f(az[k].x), acc[k].x);
            acc[k].y = fmaf(zm.y, sig_f(az[k].y), acc[k].y);
            acc[k].z = fmaf(zm.z, sig_f(az[k].z), acc[k].z);
            acc[k].w = fmaf(zm.w, sig_f(az[k].w), acc[k].w);
        }
    }

    // ---- coalesced direct stores: lane-contiguous float4 per k ----
    float4* out4 = (float4*)out;
    #pragma unroll
    for (int k = 0; k < 4; ++k) {
        const int rk = (int)r + k * q;
        if (rk < B)
            __stcs(out4 + (g + 6u * (unsigned)(k * q)), acc[k]);
    }
}

// ---------------------------------------------------------------------------
extern "C" void kernel_launch(void* const* d_in, const int* in_sizes, int n_in,
                              void* d_out, int out_size) {
    const float* x  = (const float*)d_in[0];
    const float* W  = (const float*)d_in[1];
    const float* P  = (const float*)d_in[2];
    const float* bv = (const float*)d_in[3];
    const float* bz = (const float*)d_in[4];
    const float* e  = (const float*)d_in[5];
    const float* ep = (const float*)d_in[6];
    const float* cx = (const float*)d_in[7];
    const float* cu = (const float*)d_in[8];
    const float* cU = (const float*)d_in[9];
    const float* v0 = (const float*)d_in[10];
    const float* X0 = (const float*)d_in[11];
    const float* U0 = (const float*)d_in[12];

    const int B = in_sizes[0] / 8;
    const int q = (B + 3) / 4;                 // rows per quarter
    const unsigned nG = 6u * (unsigned)q;      // threads needed
    const int grid = (int)((nG + TPB - 1) / TPB);

    if (grid > 0)
        cb_fused<<<grid, TPB>>>(x, (float*)d_out, B, q,
                                W, P, bv, bz, e, ep, cx, cu, cU, v0, X0, U0);
}

// round 5
// speedup vs baseline: 1.4781x; 1.4781x over previous
#include <cuda_runtime.h>

#define TPB  256
#define RPB  256                          // rows per block = 1 per thread
#define SROW 25                           // staging stride (odd -> STS conflict-free)
#define STAGE_W  (RPB * SROW)             // 6400 words
#define PD_BASE  STAGE_W                  // 24 x 8 words: 0.1*P rows (two float4 each)
#define C0_BASE  (PD_BASE + 192)          // 24 words: c0
#define PZ_BASE  (C0_BASE + 24)           // 24 x 8 words: pe*sp(P) rows (16B aligned)
#define A1_BASE  (PZ_BASE + 192)          // 24 words
#define ZM_BASE  (A1_BASE + 24)           // 24 words
#define FLAG_OFS (ZM_BASE + 24)
#define SMEM_W   (FLAG_OFS + 8)           // 6864 words = 27.5KB -> 8 blocks/SM

__device__ __forceinline__ float sp_f(float x) {      // fast softplus
    return fmaxf(x, 0.0f) + __logf(1.0f + __expf(-fabsf(x)));
}
__device__ __forceinline__ float sig_f(float x) {
    return 1.0f / (1.0f + __expf(-x));
}

__global__ void __launch_bounds__(TPB, 8)
cb_fused(const float* __restrict__ x, float* __restrict__ out, int B,
         const float* __restrict__ W,  const float* __restrict__ P,
         const float* __restrict__ bv, const float* __restrict__ bz,
         const float* __restrict__ e,  const float* __restrict__ ep,
         const float* __restrict__ cx, const float* __restrict__ cu,
         const float* __restrict__ cU, const float* __restrict__ v0,
         const float* __restrict__ X0, const float* __restrict__ U0)
{
    __shared__ float sm[SMEM_W];
    const int t = threadIdx.x;
    const int row = blockIdx.x * RPB + t;       // lane <-> consecutive batch row

    // ---- x loads first (perfectly coalesced), latency overlaps prologue ----
    float xa[8];
    #pragma unroll
    for (int i = 0; i < 8; ++i)
        xa[i] = (row < B) ? x[(size_t)i * (size_t)B + row] : 0.0f;

    // ---- prologue: batch-invariant math (scratch aliases staging region) ----
    {
        float* rS  = sm;            // 24
        float* wS  = sm + 24;       // 24
        float* pkr = sm + 48;       // 192
        float* pwr = sm + 240;      // 192

        if (t < 24) {
            float v0v = v0[t];
            float rv  = sig_f(v0v);
            rS[t] = rv;
            float zx = 0.001f + 0.099f * sig_f(cx[t]);
            float X  = zx + (1.0f - zx) * X0[t] - U0[t] * X0[t] * rv;  // delta_t=1
            float zu   = 0.001f + 0.099f * sig_f(cu[t]);
            float Ucap = 0.9f * sig_f(cU[t]);
            float U = Ucap * zu + (1.0f - zu) * U0[t] + Ucap * (1.0f - U0[t]) * rv;
            U = fminf(fmaxf(U, Ucap), 1.0f);
            wS[t] = U * X * rv;
            sm[ZM_BASE + t] = -0.1f * v0v;
        }
        if (t == 0) {
            int f = 0;
            #pragma unroll
            for (int j = 0; j < 24; ++j) f |= (v0[j] != 0.0f);
            sm[FLAG_OFS] = (float)f;
        }
        __syncthreads();

        if (t < 192) {
            const int h = t >> 3;                // 0..23
            const int i = t & 7;                 // 0..7
            float kr = 0.0f, wur = 0.0f;
            #pragma unroll
            for (int jj = 0; jj < 3; ++jj) {
                int j = i * 3 + jj;
                float Wv = W[h * 24 + j];
                kr  += sp_f(Wv) * rS[j];
                wur += Wv * wS[j];
            }
            pkr[h * 8 + i] = kr;
            pwr[h * 8 + i] = wur;
            float pe = sp_f(ep[0]);
            float Pv = P[h * 8 + i];             // P is (H, IN) row-major
            sm[PD_BASE + h * 8 + i] = 0.1f * Pv;
            sm[PZ_BASE + h * 8 + i] = pe * sp_f(Pv);
        }
        __syncthreads();

        if (t < 24) {
            float kr = 0.0f, wur = 0.0f;
            #pragma unroll
            for (int k = 0; k < 8; ++k) { kr += pkr[t * 8 + k]; wur += pwr[t * 8 + k]; }
            float ke = sp_f(e[0]);
            sm[A1_BASE + t] = ke * kr + bz[t];                    // a1
            sm[C0_BASE + t] = v0[t] + 0.1f * (wur + bv[t]);       // c0
        }
        __syncthreads();
    }

    const bool slow = (sm[FLAG_OFS] != 0.0f);

    // ---- hoist all 24 c0 into registers (6 x LDS.128, once) ----
    float4 c0v[6];
    #pragma unroll
    for (int j = 0; j < 6; ++j)
        c0v[j] = ((const float4*)(sm + C0_BASE))[j];

    // ---- main: 24 h per row; per h = 2 broadcast LDS.128 + 8 FFMA + 1 STS ----
    #pragma unroll
    for (int h = 0; h < 24; ++h) {
        const float4 wA = ((const float4*)(sm + PD_BASE + h * 8))[0];
        const float4 wB = ((const float4*)(sm + PD_BASE + h * 8))[1];
        float v = ((const float*)c0v)[h];
        v = fmaf(wA.x, xa[0], v);
        v = fmaf(wA.y, xa[1], v);
        v = fmaf(wA.z, xa[2], v);
        v = fmaf(wA.w, xa[3], v);
        v = fmaf(wB.x, xa[4], v);
        v = fmaf(wB.y, xa[5], v);
        v = fmaf(wB.z, xa[6], v);
        v = fmaf(wB.w, xa[7], v);

        if (slow) {
            // General case (v0 != 0): v += sig(a1 + Pz@x) * (-0.1*v0[h]). Exact.
            const float4 zA = ((const float4*)(sm + PZ_BASE + h * 8))[0];
            const float4 zB = ((const float4*)(sm + PZ_BASE + h * 8))[1];
            float a = sm[A1_BASE + h];
            a = fmaf(zA.x, xa[0], a);
            a = fmaf(zA.y, xa[1], a);
            a = fmaf(zA.z, xa[2], a);
            a = fmaf(zA.w, xa[3], a);
            a = fmaf(zB.x, xa[4], a);
            a = fmaf(zB.y, xa[5], a);
            a = fmaf(zB.z, xa[6], a);
            a = fmaf(zB.w, xa[7], a);
            v = fmaf(sm[ZM_BASE + h], sig_f(a), v);
        }

        sm[t * SROW + h] = v;                 // stride 25: conflict-free STS
    }
    __syncthreads();

    // ---- coalesced writeout: block owns float4 range [blockIdx*1536, +1536) ----
    const unsigned totF4  = (unsigned)B * 6u;
    const unsigned baseF4 = (unsigned)blockIdx.x * 1536u;
    float4* out4 = (float4*)out;
    #pragma unroll
    for (int k = 0; k < 6; ++k) {
        unsigned g = (unsigned)(k * 256 + t);        // 0..1535
        if (baseF4 + g < totF4) {
            unsigned r = g / 6u;                     // row within block
            unsigned c = g - r * 6u;                 // float4 column
            const float* pp = sm + r * SROW + c * 4u;
            float4 o;
            o.x = pp[0]; o.y = pp[1]; o.z = pp[2]; o.w = pp[3];
            __stcs(out4 + (baseF4 + g), o);
        }
    }
}

// ---------------------------------------------------------------------------
extern "C" void kernel_launch(void* const* d_in, const int* in_sizes, int n_in,
                              void* d_out, int out_size) {
    const float* x  = (const float*)d_in[0];
    const float* W  = (const float*)d_in[1];
    const float* P  = (const float*)d_in[2];
    const float* bv = (const float*)d_in[3];
    const float* bz = (const float*)d_in[4];
    const float* e  = (const float*)d_in[5];
    const float* ep = (const float*)d_in[6];
    const float* cx = (const float*)d_in[7];
    const float* cu = (const float*)d_in[8];
    const float* cU = (const float*)d_in[9];
    const float* v0 = (const float*)d_in[10];
    const float* X0 = (const float*)d_in[11];
    const float* U0 = (const float*)d_in[12];

    const int B  = in_sizes[0] / 8;
    const int nb = (B + RPB - 1) / RPB;

    if (nb > 0)
        cb_fused<<<nb, TPB>>>(x, (float*)d_out, B,
                              W, P, bv, bz, e, ep, cx, cu, cU, v0, X0, U0);
}